// round 4
// baseline (speedup 1.0000x reference)
#include <cuda_runtime.h>

// Problem constants
#define NN 32
#define CC 64
#define TTT 256
#define VV 25
#define RR 8
#define OO 64
#define SS 3
#define STREAM_ELEMS (NN*OO*TTT*VV)   // 13,107,200
#define NTV (NN*TTT*VV)               // 204,800

typedef unsigned long long u64;

__device__ __forceinline__ u64 pack2(float lo, float hi) {
    u64 r; asm("mov.b64 %0,{%1,%2};" : "=l"(r) : "f"(lo), "f"(hi)); return r;
}
__device__ __forceinline__ void unpack2(u64 p, float& lo, float& hi) {
    asm("mov.b64 {%0,%1},%2;" : "=f"(lo), "=f"(hi) : "l"(p));
}
__device__ __forceinline__ void ffma2(u64& d, u64 a, u64 b) {
    asm("fma.rn.f32x2 %0,%1,%2,%0;" : "+l"(d) : "l"(a), "l"(b));
}

// ---------------- scratch ----------------------------------------------------
__device__ float g_xm[2][NN][CC][VV];
__device__ float g_r[2][SS][NN][RR][VV];
__device__ float g_a[2][SS][NN][OO][VV*VV];        // ~30.7 MB
__device__ float g_sum[2][OO];
__device__ float g_sumsq[2][OO];
__device__ float g_mean[2][OO];
__device__ float g_rstd[2][OO];

// ---------------- K1: mean over T (+ zero stats in block 0) ------------------
__global__ void k_mean(const float* __restrict__ x1, const float* __restrict__ x2) {
    int b   = blockIdx.x;
    int tid = threadIdx.x;
    if (b == 0 && tid < 2*OO) {
        ((float*)g_sum)[tid]   = 0.f;
        ((float*)g_sumsq)[tid] = 0.f;
    }
    int s   = b / (NN*CC);
    int rem = b % (NN*CC);
    const float* x = s ? x2 : x1;
    const float* p = x + (size_t)rem * TTT * VV;
    float acc = 0.f;
    #pragma unroll
    for (int k = 0; k < 8; k++) acc += p[tid + k*800];
    __shared__ float part[800];
    part[tid] = acc;
    __syncthreads();
    if (tid < VV) {
        float sum = 0.f;
        #pragma unroll
        for (int tg = 0; tg < 32; tg++) sum += part[tg*VV + tid];
        g_xm[s][rem/CC][rem%CC][tid] = sum * (1.0f/TTT);
    }
}

// ---------------- K2: r = w·xm + b ------------------------------------------
__global__ void k_r(const float* __restrict__ c1w, const float* __restrict__ c1b,
                    const float* __restrict__ c2w, const float* __restrict__ c2b) {
    int i = blockIdx.x / NN, n = blockIdx.x % NN;
    int tid = threadIdx.x;
    if (tid >= 2*RR*VV) return;
    int s  = tid / (RR*VV);
    int rv = tid % (RR*VV);
    int r  = rv / VV, v = rv % VV;
    const float* w  = s ? c2w : c1w;
    const float* bb = s ? c2b : c1b;
    const float* wrow = w + (i*RR + r)*CC;
    const float* xm   = &g_xm[s][n][0][v];
    float acc = bb[i*RR + r];
    #pragma unroll 8
    for (int c = 0; c < CC; c++) acc += wrow[c] * xm[c*VV];
    g_r[s][i][n][r][v] = acc;
}

// ---------------- K3: rel=tanh(r1-r2); a1,a2 = W·rel + bias + PA/alpha -------
__global__ void k_a(const float* __restrict__ PA, const float* __restrict__ alpha,
                    const float* __restrict__ c5w, const float* __restrict__ c5b,
                    const float* __restrict__ c6w, const float* __restrict__ c6b) {
    int bx = blockIdx.x;                 // o-quarter
    int i  = blockIdx.y / NN, n = blockIdx.y % NN;
    __shared__ float rel[RR][VV*VV];
    __shared__ float r1s[RR][VV], r2s[RR][VV];
    __shared__ u64  wp_s[16*RR];
    int tid = threadIdx.x;
    if (tid < RR*VV) {
        int r = tid/VV, v = tid%VV;
        r1s[r][v] = g_r[0][i][n][r][v];
        r2s[r][v] = g_r[1][i][n][r][v];
    }
    if (tid < 16*RR) {
        int o = tid / RR, r = tid % RR;
        int idx = (i*OO + bx*16 + o)*RR + r;
        wp_s[tid] = pack2(c5w[idx], c6w[idx]);
    }
    __syncthreads();
    for (int q = tid; q < RR*VV*VV; q += 256) {
        int r = q / (VV*VV), uv = q % (VV*VV);
        int u = uv / VV, v = uv % VV;
        rel[r][uv] = tanhf(r1s[r][u] - r2s[r][v]);
    }
    __syncthreads();
    float al = alpha[0];
    for (int q = tid; q < 16*VV*VV; q += 256) {
        int ol = q / (VV*VV), uv = q % (VV*VV);
        int o  = bx*16 + ol;
        float a1 = c5b[i*OO + o] + PA[i*VV*VV + uv];
        float a2 = c6b[i*OO + o] + al;
        u64 acc = pack2(a1, a2);
        #pragma unroll
        for (int r = 0; r < RR; r++) {
            float rv = rel[r][uv];
            ffma2(acc, wp_s[ol*RR + r], pack2(rv, rv));
        }
        float lo, hi; unpack2(acc, lo, hi);
        g_a[0][i][n][o][uv] = lo;
        g_a[1][i][n][o][uv] = hi;
    }
}

// ---------------- K4: fused conv1x1 + graph contraction ----------------------
// block = (t-tile 32, o-half 32, one (s,n)); 512 threads, 1 block/SM.
// dyn smem layout (bytes):
//   [0)        wsd : u64[64][16]   (w dup pairs)          8192
//   [8192)     bpr : u64[16]       (bias dup pairs)        128
//   [8320)     x3s : f32[32][832]  (conv tile, row 26)  106496
//   [114816)   as_ : f32[32][650]  (a rows, row 26)      83200
#define SM_WSD   0
#define SM_BPR   8192
#define SM_X3S   8320
#define SM_AS    114816
#define SMEM_BYTES (114816 + 83200)

__global__ void __launch_bounds__(512, 1)
k_main(const float* __restrict__ x1, const float* __restrict__ x2,
       const float* __restrict__ c3w, const float* __restrict__ c3b,
       const float* __restrict__ c4w, const float* __restrict__ c4b,
       float* __restrict__ out) {
    extern __shared__ __align__(16) char smraw[];
    u64*   wsd = (u64*)(smraw + SM_WSD);
    u64*   bpr = (u64*)(smraw + SM_BPR);
    float* x3s = (float*)(smraw + SM_X3S);
    float* as_ = (float*)(smraw + SM_AS);

    int tt0   = blockIdx.x * 32;
    int obase = blockIdx.y * 32;
    int z     = blockIdx.z;
    int s     = z >> 5;
    int n     = z & 31;
    const float* x  = s ? x2  : x1;
    const float* cw = s ? c4w : c3w;
    const float* cb = s ? c4b : c3b;
    float* yout = out + (size_t)s * STREAM_ELEMS;

    int tid  = threadIdx.x;
    int wid  = tid >> 5;
    int lane = tid & 31;

    float yacc[2][VV];
    #pragma unroll
    for (int h = 0; h < 2; h++)
        #pragma unroll
        for (int u = 0; u < VV; u++) yacc[h][u] = 0.f;

    const float* xbase = x + ((size_t)n*CC)*TTT*VV + (size_t)tt0*VV;

    for (int i = 0; i < SS; i++) {
        // ---- stage: dup weight pairs, dup bias pairs, a-slice (padded rows)
        #pragma unroll
        for (int rep = 0; rep < 2; rep++) {
            int q = tid + rep*512;          // 0..1023 : c*16 + j
            int c = q >> 4, j = q & 15;
            int ob = (i*OO + obase + 2*j)*CC + c;
            wsd[q] = pack2(cw[ob], cw[ob + CC]);
        }
        if (tid < 16)
            bpr[tid] = pack2(cb[i*OO + obase + 2*tid], cb[i*OO + obase + 2*tid + 1]);
        {
            const float4* asrc = (const float4*)&g_a[s][i][n][obase][0]; // 32*625 floats, 16B-aligned
            for (int q = tid; q < 5000; q += 512) {
                float4 vq = asrc[q];
                int e = q*4;
                #pragma unroll
                for (int k = 0; k < 4; k++) {
                    int ee = e + k;
                    int ol = ee / 625;
                    int r  = ee - ol*625;
                    int u  = r / 25, v = r - u*25;
                    float val = (k==0)?vq.x:(k==1)?vq.y:(k==2)?vq.z:vq.w;
                    as_[ol*650 + u*26 + v] = val;
                }
            }
        }
        __syncthreads();

        // ---- phase 1: x3[ol][t][v] = sum_c w·x + b, for 32 channels
        if (tid < 400) {
            #pragma unroll
            for (int rep = 0; rep < 2; rep++) {
                int p = tid + rep*400;        // 0..799 position in 32x25 tile
                u64 acc2[16];
                #pragma unroll
                for (int j = 0; j < 16; j++) acc2[j] = bpr[j];
                const float* xp = xbase + p;
                #pragma unroll 4
                for (int c = 0; c < CC; c++) {
                    float xv = xp[(size_t)c*TTT*VV];
                    u64 xb = pack2(xv, xv);
                    const u64* wrow = &wsd[c*16];
                    #pragma unroll
                    for (int j = 0; j < 16; j++) ffma2(acc2[j], xb, wrow[j]);
                }
                int t = p / 25, v = p - t*25;
                int tv = t*26 + v;
                #pragma unroll
                for (int j = 0; j < 16; j++) {
                    float lo, hi; unpack2(acc2[j], lo, hi);
                    x3s[(2*j  )*832 + tv] = lo;
                    x3s[(2*j+1)*832 + tv] = hi;
                }
            }
        }
        __syncthreads();

        // ---- phase 2: y[ol][t][u] += sum_v a[ol][u][v] * x3[ol][t][v]
        #pragma unroll
        for (int h = 0; h < 2; h++) {
            int ol = wid + h*16;
            const u64* xrow = (const u64*)&x3s[ol*832 + lane*26];
            u64 xp[12];
            #pragma unroll
            for (int j = 0; j < 12; j++) xp[j] = xrow[j];
            float xlast = x3s[ol*832 + lane*26 + 24];
            #pragma unroll
            for (int u = 0; u < VV; u++) {
                const u64* arow = (const u64*)&as_[ol*650 + u*26];
                u64 accA = 0ull, accB = 0ull;
                #pragma unroll
                for (int j = 0; j < 12; j += 2) {
                    ffma2(accA, arow[j],   xp[j]);
                    ffma2(accB, arow[j+1], xp[j+1]);
                }
                float a0, a1, b0, b1;
                unpack2(accA, a0, a1); unpack2(accB, b0, b1);
                yacc[h][u] += (a0 + a1) + (b0 + b1) + as_[ol*650 + u*26 + 24] * xlast;
            }
        }
        __syncthreads();
    }

    // ---- write raw y + channel stats
    #pragma unroll
    for (int h = 0; h < 2; h++) {
        int o = obase + wid + h*16;
        int t = tt0 + lane;
        float* yp = yout + ((size_t)(n*OO + o) * TTT + t) * VV;
        float ls = 0.f, lq = 0.f;
        #pragma unroll
        for (int u = 0; u < VV; u++) {
            float yv = yacc[h][u];
            yp[u] = yv;
            ls += yv;
            lq += yv*yv;
        }
        #pragma unroll
        for (int off = 16; off; off >>= 1) {
            ls += __shfl_down_sync(0xffffffffu, ls, off);
            lq += __shfl_down_sync(0xffffffffu, lq, off);
        }
        if (lane == 0) {
            atomicAdd(&g_sum[s][o],   ls);
            atomicAdd(&g_sumsq[s][o], lq);
        }
    }
}

// ---------------- K5 ---------------------------------------------------------
__global__ void k_stats() {
    int i = threadIdx.x;
    if (i < 2*OO) {
        int s = i / OO, o = i % OO;
        float m = g_sum[s][o] * (1.0f/NTV);
        float v = g_sumsq[s][o] * (1.0f/NTV) - m*m;
        g_mean[s][o] = m;
        g_rstd[s][o] = rsqrtf(v + 1e-5f);
    }
}

// ---------------- K6: BN + residual + ReLU -----------------------------------
__global__ void k_bn(const float* __restrict__ x1, const float* __restrict__ x2,
                     const float* __restrict__ bn1w, const float* __restrict__ bn1b,
                     const float* __restrict__ bn2w, const float* __restrict__ bn2b,
                     float* __restrict__ out) {
    const long total4 = 2L * STREAM_ELEMS / 4;
    long stride = (long)gridDim.x * blockDim.x;
    for (long q = (long)blockIdx.x * blockDim.x + threadIdx.x; q < total4; q += stride) {
        long e   = q * 4;
        int  s   = (int)(e / STREAM_ELEMS);
        long rem = e % STREAM_ELEMS;
        int  o   = (int)((rem / (TTT*VV)) % OO);
        const float* bw = s ? bn2w : bn1w;
        const float* bb = s ? bn2b : bn1b;
        const float* xr = s ? x2   : x1;
        float m  = g_mean[s][o], rs = g_rstd[s][o];
        float sc = rs * bw[o];
        float sh = bb[o] - m * sc;
        float4 yv = ((float4*)out)[q];
        float4 xv = ((const float4*)xr)[rem/4];
        yv.x = fmaxf(fmaf(yv.x, sc, sh) + xv.x, 0.f);
        yv.y = fmaxf(fmaf(yv.y, sc, sh) + xv.y, 0.f);
        yv.z = fmaxf(fmaf(yv.z, sc, sh) + xv.z, 0.f);
        yv.w = fmaxf(fmaf(yv.w, sc, sh) + xv.w, 0.f);
        ((float4*)out)[q] = yv;
    }
}

// ---------------- launcher ---------------------------------------------------
extern "C" void kernel_launch(void* const* d_in, const int* in_sizes, int n_in,
                              void* d_out, int out_size) {
    const float* x1    = (const float*)d_in[0];
    const float* x2    = (const float*)d_in[1];
    const float* PA    = (const float*)d_in[2];
    const float* alpha = (const float*)d_in[3];
    const float* c1w   = (const float*)d_in[4];
    const float* c1b   = (const float*)d_in[5];
    const float* c2w   = (const float*)d_in[6];
    const float* c2b   = (const float*)d_in[7];
    const float* c3w   = (const float*)d_in[8];
    const float* c3b   = (const float*)d_in[9];
    const float* c4w   = (const float*)d_in[10];
    const float* c4b   = (const float*)d_in[11];
    const float* c5w   = (const float*)d_in[12];
    const float* c5b   = (const float*)d_in[13];
    const float* c6w   = (const float*)d_in[14];
    const float* c6b   = (const float*)d_in[15];
    const float* bn1w  = (const float*)d_in[16];
    const float* bn1b  = (const float*)d_in[17];
    const float* bn2w  = (const float*)d_in[18];
    const float* bn2b  = (const float*)d_in[19];
    float* out = (float*)d_out;

    cudaFuncSetAttribute(k_main, cudaFuncAttributeMaxDynamicSharedMemorySize, SMEM_BYTES);

    k_mean<<<2*NN*CC, 800>>>(x1, x2);
    k_r<<<SS*NN, 512>>>(c1w, c1b, c2w, c2b);
    k_a<<<dim3(4, SS*NN), 256>>>(PA, alpha, c5w, c5b, c6w, c6b);
    k_main<<<dim3(TTT/32, 2, 2*NN), 512, SMEM_BYTES>>>(x1, x2, c3w, c3b, c4w, c4b, out);
    k_stats<<<1, 128>>>();
    k_bn<<<8192, 256>>>(x1, x2, bn1w, bn1b, bn2w, bn2b, out);
}

// round 5
// speedup vs baseline: 1.1447x; 1.1447x over previous
#include <cuda_runtime.h>

// Problem constants
#define NN 32
#define CC 64
#define TTT 256
#define VV 25
#define RR 8
#define OO 64
#define SS 3
#define STREAM_ELEMS (NN*OO*TTT*VV)   // 13,107,200
#define NTV (NN*TTT*VV)               // 204,800

typedef unsigned long long u64;

__device__ __forceinline__ u64 pack2(float lo, float hi) {
    u64 r; asm("mov.b64 %0,{%1,%2};" : "=l"(r) : "f"(lo), "f"(hi)); return r;
}
__device__ __forceinline__ void unpack2(u64 p, float& lo, float& hi) {
    asm("mov.b64 {%0,%1},%2;" : "=f"(lo), "=f"(hi) : "l"(p));
}
__device__ __forceinline__ void ffma2(u64& d, u64 a, u64 b) {
    asm("fma.rn.f32x2 %0,%1,%2,%0;" : "+l"(d) : "l"(a), "l"(b));
}

// ---------------- scratch ----------------------------------------------------
__device__ float g_xm[2][NN][CC][VV];
__device__ float g_r[2][SS][NN][RR][VV];
__device__ float g_a[2][SS][NN][OO][VV*VV];        // ~30.7 MB
__device__ float g_sum[2][OO];
__device__ float g_sumsq[2][OO];
__device__ float g_mean[2][OO];
__device__ float g_rstd[2][OO];

// ---------------- K1: mean over T (+ zero stats in block 0) ------------------
__global__ void k_mean(const float* __restrict__ x1, const float* __restrict__ x2) {
    int b   = blockIdx.x;
    int tid = threadIdx.x;
    if (b == 0 && tid < 2*OO) {
        ((float*)g_sum)[tid]   = 0.f;
        ((float*)g_sumsq)[tid] = 0.f;
    }
    int s   = b / (NN*CC);
    int rem = b % (NN*CC);
    const float* x = s ? x2 : x1;
    const float* p = x + (size_t)rem * TTT * VV;
    float acc = 0.f;
    #pragma unroll
    for (int k = 0; k < 8; k++) acc += p[tid + k*800];
    __shared__ float part[800];
    part[tid] = acc;
    __syncthreads();
    if (tid < VV) {
        float sum = 0.f;
        #pragma unroll
        for (int tg = 0; tg < 32; tg++) sum += part[tg*VV + tid];
        g_xm[s][rem/CC][rem%CC][tid] = sum * (1.0f/TTT);
    }
}

// ---------------- K2: r = w·xm + b ------------------------------------------
__global__ void k_r(const float* __restrict__ c1w, const float* __restrict__ c1b,
                    const float* __restrict__ c2w, const float* __restrict__ c2b) {
    int i = blockIdx.x / NN, n = blockIdx.x % NN;
    int tid = threadIdx.x;
    if (tid >= 2*RR*VV) return;
    int s  = tid / (RR*VV);
    int rv = tid % (RR*VV);
    int r  = rv / VV, v = rv % VV;
    const float* w  = s ? c2w : c1w;
    const float* bb = s ? c2b : c1b;
    const float* wrow = w + (i*RR + r)*CC;
    const float* xm   = &g_xm[s][n][0][v];
    float acc = bb[i*RR + r];
    #pragma unroll 8
    for (int c = 0; c < CC; c++) acc += wrow[c] * xm[c*VV];
    g_r[s][i][n][r][v] = acc;
}

// ---------------- K3: rel=tanh(r1-r2); a1,a2 = W·rel + bias + PA/alpha -------
// grid = (4, SS*NN), block 256. Incremental index math (no div/mod in loops).
__global__ void k_a(const float* __restrict__ PA, const float* __restrict__ alpha,
                    const float* __restrict__ c5w, const float* __restrict__ c5b,
                    const float* __restrict__ c6w, const float* __restrict__ c6b) {
    int bx = blockIdx.x;                 // o-quarter
    int i  = blockIdx.y / NN, n = blockIdx.y % NN;
    __shared__ float rel[RR][VV*VV];
    __shared__ float r1s[RR][VV], r2s[RR][VV];
    __shared__ u64  wp_s[16*RR];
    int tid = threadIdx.x;
    if (tid < RR*VV) {
        int r = tid/VV, v = tid%VV;
        r1s[r][v] = g_r[0][i][n][r][v];
        r2s[r][v] = g_r[1][i][n][r][v];
    }
    if (tid < 16*RR) {
        int o = tid / RR, r = tid % RR;
        int idx = (i*OO + bx*16 + o)*RR + r;
        wp_s[tid] = pack2(c5w[idx], c6w[idx]);
    }
    __syncthreads();
    {
        int r = 0, uv = tid;             // tid < 256 <= 625
        int u = uv / VV, v = uv - u*VV;
        while (r < RR) {
            rel[r][uv] = tanhf(r1s[r][u] - r2s[r][v]);
            uv += 256;
            if (uv >= VV*VV) { uv -= VV*VV; r++; }
            u = uv / VV; v = uv - u*VV;
        }
    }
    __syncthreads();
    float al = alpha[0];
    {
        int ol = 0, uv = tid;
        while (ol < 16) {
            int o = bx*16 + ol;
            float a1 = c5b[i*OO + o] + PA[i*VV*VV + uv];
            float a2 = c6b[i*OO + o] + al;
            u64 acc = pack2(a1, a2);
            #pragma unroll
            for (int r = 0; r < RR; r++) {
                float rv = rel[r][uv];
                ffma2(acc, wp_s[ol*RR + r], pack2(rv, rv));
            }
            float lo, hi; unpack2(acc, lo, hi);
            g_a[0][i][n][o][uv] = lo;
            g_a[1][i][n][o][uv] = hi;
            uv += 256;
            if (uv >= VV*VV) { uv -= VV*VV; ol++; }
        }
    }
}

// ---------------- K4: fused conv1x1 + graph contraction ----------------------
// block = (t-tile 32, o-tile 16, one (s,n)); 512 threads, 2 blocks/SM.
// dyn smem (bytes):
//   [0)      wsd : u64[64][8]    (w dup pairs)          4096
//   [4096)   bpr : u64[8]        (bias dup pairs)         64
//   [4160)   x3s : f32[16][832]  (conv tile, row 26)   53248
//   [57408)  as_ : f32[16][650]  (a rows, row 26)      41600
#define SM_WSD   0
#define SM_BPR   4096
#define SM_X3S   4160
#define SM_AS    57408
#define SMEM_BYTES (57408 + 41600)     // 99008

__global__ void __launch_bounds__(512, 2)
k_main(const float* __restrict__ x1, const float* __restrict__ x2,
       const float* __restrict__ c3w, const float* __restrict__ c3b,
       const float* __restrict__ c4w, const float* __restrict__ c4b,
       float* __restrict__ out) {
    extern __shared__ __align__(16) char smraw[];
    u64*   wsd = (u64*)(smraw + SM_WSD);
    u64*   bpr = (u64*)(smraw + SM_BPR);
    float* x3s = (float*)(smraw + SM_X3S);
    float* as_ = (float*)(smraw + SM_AS);

    int tt0   = blockIdx.x * 32;
    int obase = blockIdx.y * 16;
    int z     = blockIdx.z;
    int s     = z >> 5;
    int n     = z & 31;
    const float* x  = s ? x2  : x1;
    const float* cw = s ? c4w : c3w;
    const float* cb = s ? c4b : c3b;
    float* yout = out + (size_t)s * STREAM_ELEMS;

    int tid  = threadIdx.x;
    int wid  = tid >> 5;                // phase-2: warp -> o within tile (0..15)
    int lane = tid & 31;                // phase-2: lane -> t within tile

    float yacc[VV];
    #pragma unroll
    for (int u = 0; u < VV; u++) yacc[u] = 0.f;

    const float* xbase = x + ((size_t)n*CC)*TTT*VV + (size_t)tt0*VV;

    for (int i = 0; i < SS; i++) {
        // ---- stage: dup weight pairs (512 = one per thread), bias, a-slice
        {
            int c = tid >> 3, j = tid & 7;
            int ob = (i*OO + obase + 2*j)*CC + c;
            wsd[tid] = pack2(cw[ob], cw[ob + CC]);
        }
        if (tid < 8)
            bpr[tid] = pack2(cb[i*OO + obase + 2*tid], cb[i*OO + obase + 2*tid + 1]);
        {
            const float4* asrc = (const float4*)&g_a[s][i][n][obase][0]; // 16*625 floats
            for (int q = tid; q < 2500; q += 512) {
                float4 vq = asrc[q];
                int e = q*4;
                #pragma unroll
                for (int k = 0; k < 4; k++) {
                    int ee = e + k;
                    int ol = ee / 625;
                    int r  = ee - ol*625;
                    int u  = r / 25, v = r - u*25;
                    float val = (k==0)?vq.x:(k==1)?vq.y:(k==2)?vq.z:vq.w;
                    as_[ol*650 + u*26 + v] = val;
                }
            }
        }
        __syncthreads();

        // ---- phase 1: x3[ol][t][v] = sum_c w·x + b  (2 sequential passes)
        if (tid < 400) {
            #pragma unroll
            for (int rep = 0; rep < 2; rep++) {
                int p = tid + rep*400;        // 0..799 position in 32x25 tile
                u64 acc[8];
                #pragma unroll
                for (int j = 0; j < 8; j++) acc[j] = bpr[j];
                const float* xp = xbase + p;
                #pragma unroll 4
                for (int c = 0; c < CC; c++) {
                    float xv = xp[(size_t)c*TTT*VV];
                    u64 xb = pack2(xv, xv);
                    const ulonglong2* wrow = (const ulonglong2*)&wsd[c*8];
                    ulonglong2 w01 = wrow[0], w23 = wrow[1], w45 = wrow[2], w67 = wrow[3];
                    ffma2(acc[0], xb, w01.x); ffma2(acc[1], xb, w01.y);
                    ffma2(acc[2], xb, w23.x); ffma2(acc[3], xb, w23.y);
                    ffma2(acc[4], xb, w45.x); ffma2(acc[5], xb, w45.y);
                    ffma2(acc[6], xb, w67.x); ffma2(acc[7], xb, w67.y);
                }
                int t = p / 25, v = p - t*25;
                int tv = t*26 + v;
                #pragma unroll
                for (int j = 0; j < 8; j++) {
                    float lo, hi; unpack2(acc[j], lo, hi);
                    x3s[(2*j  )*832 + tv] = lo;
                    x3s[(2*j+1)*832 + tv] = hi;
                }
            }
        }
        __syncthreads();

        // ---- phase 2: y[t][u] += sum_v a[wid][u][v] * x3[wid][t][v]
        {
            const u64* xrow = (const u64*)&x3s[wid*832 + lane*26];
            u64 xp[12];
            #pragma unroll
            for (int j = 0; j < 12; j++) xp[j] = xrow[j];
            float xlast = x3s[wid*832 + lane*26 + 24];
            #pragma unroll
            for (int u = 0; u < VV; u++) {
                const u64* arow = (const u64*)&as_[wid*650 + u*26];
                u64 accA = 0ull, accB = 0ull;
                #pragma unroll
                for (int j = 0; j < 12; j += 2) {
                    ffma2(accA, arow[j],   xp[j]);
                    ffma2(accB, arow[j+1], xp[j+1]);
                }
                float a0, a1, b0, b1;
                unpack2(accA, a0, a1); unpack2(accB, b0, b1);
                yacc[u] += (a0 + a1) + (b0 + b1) + as_[wid*650 + u*26 + 24] * xlast;
            }
        }
        __syncthreads();
    }

    // ---- write raw y + channel stats
    {
        int o = obase + wid;
        int t = tt0 + lane;
        float* yp = yout + ((size_t)(n*OO + o) * TTT + t) * VV;
        float ls = 0.f, lq = 0.f;
        #pragma unroll
        for (int u = 0; u < VV; u++) {
            float yv = yacc[u];
            yp[u] = yv;
            ls += yv;
            lq += yv*yv;
        }
        #pragma unroll
        for (int off = 16; off; off >>= 1) {
            ls += __shfl_down_sync(0xffffffffu, ls, off);
            lq += __shfl_down_sync(0xffffffffu, lq, off);
        }
        if (lane == 0) {
            atomicAdd(&g_sum[s][o],   ls);
            atomicAdd(&g_sumsq[s][o], lq);
        }
    }
}

// ---------------- K5 ---------------------------------------------------------
__global__ void k_stats() {
    int i = threadIdx.x;
    if (i < 2*OO) {
        int s = i / OO, o = i % OO;
        float m = g_sum[s][o] * (1.0f/NTV);
        float v = g_sumsq[s][o] * (1.0f/NTV) - m*m;
        g_mean[s][o] = m;
        g_rstd[s][o] = rsqrtf(v + 1e-5f);
    }
}

// ---------------- K6: BN + residual + ReLU -----------------------------------
__global__ void k_bn(const float* __restrict__ x1, const float* __restrict__ x2,
                     const float* __restrict__ bn1w, const float* __restrict__ bn1b,
                     const float* __restrict__ bn2w, const float* __restrict__ bn2b,
                     float* __restrict__ out) {
    const long total4 = 2L * STREAM_ELEMS / 4;
    long stride = (long)gridDim.x * blockDim.x;
    for (long q = (long)blockIdx.x * blockDim.x + threadIdx.x; q < total4; q += stride) {
        long e   = q * 4;
        int  s   = (int)(e / STREAM_ELEMS);
        long rem = e % STREAM_ELEMS;
        int  o   = (int)((rem / (TTT*VV)) % OO);
        const float* bw = s ? bn2w : bn1w;
        const float* bb = s ? bn2b : bn1b;
        const float* xr = s ? x2   : x1;
        float m  = g_mean[s][o], rs = g_rstd[s][o];
        float sc = rs * bw[o];
        float sh = bb[o] - m * sc;
        float4 yv = ((float4*)out)[q];
        float4 xv = ((const float4*)xr)[rem/4];
        yv.x = fmaxf(fmaf(yv.x, sc, sh) + xv.x, 0.f);
        yv.y = fmaxf(fmaf(yv.y, sc, sh) + xv.y, 0.f);
        yv.z = fmaxf(fmaf(yv.z, sc, sh) + xv.z, 0.f);
        yv.w = fmaxf(fmaf(yv.w, sc, sh) + xv.w, 0.f);
        ((float4*)out)[q] = yv;
    }
}

// ---------------- launcher ---------------------------------------------------
extern "C" void kernel_launch(void* const* d_in, const int* in_sizes, int n_in,
                              void* d_out, int out_size) {
    const float* x1    = (const float*)d_in[0];
    const float* x2    = (const float*)d_in[1];
    const float* PA    = (const float*)d_in[2];
    const float* alpha = (const float*)d_in[3];
    const float* c1w   = (const float*)d_in[4];
    const float* c1b   = (const float*)d_in[5];
    const float* c2w   = (const float*)d_in[6];
    const float* c2b   = (const float*)d_in[7];
    const float* c3w   = (const float*)d_in[8];
    const float* c3b   = (const float*)d_in[9];
    const float* c4w   = (const float*)d_in[10];
    const float* c4b   = (const float*)d_in[11];
    const float* c5w   = (const float*)d_in[12];
    const float* c5b   = (const float*)d_in[13];
    const float* c6w   = (const float*)d_in[14];
    const float* c6b   = (const float*)d_in[15];
    const float* bn1w  = (const float*)d_in[16];
    const float* bn1b  = (const float*)d_in[17];
    const float* bn2w  = (const float*)d_in[18];
    const float* bn2b  = (const float*)d_in[19];
    float* out = (float*)d_out;

    cudaFuncSetAttribute(k_main, cudaFuncAttributeMaxDynamicSharedMemorySize, SMEM_BYTES);

    k_mean<<<2*NN*CC, 800>>>(x1, x2);
    k_r<<<SS*NN, 512>>>(c1w, c1b, c2w, c2b);
    k_a<<<dim3(4, SS*NN), 256>>>(PA, alpha, c5w, c5b, c6w, c6b);
    k_main<<<dim3(TTT/32, OO/16, 2*NN), 512, SMEM_BYTES>>>(x1, x2, c3w, c3b, c4w, c4b, out);
    k_stats<<<1, 128>>>();
    k_bn<<<8192, 256>>>(x1, x2, bn1w, bn1b, bn2w, bn2b, out);
}